// round 15
// baseline (speedup 1.0000x reference)
#include <cuda_runtime.h>
#include <cuda_fp16.h>
#include <math.h>
#include <stdint.h>

#define NN 50000
#define NE 600000
#define DD 128
#define NND (NN * DD)
#define TROWS 128
#define NT ((NN + TROWS - 1) / TROWS)   // 391 tiles
#define NTHR 512
#define RSTR 272                         // smem row stride in bytes (17*16)

// ---- smem byte offsets ----
#define SM_BH   0                        // B-hi: 256 rows x 272B
#define SM_BL   69632                    // B-lo
#define SM_A0   139264                   // A buf: 128 rows x 272B
#define SM_A1   174080                   // A buf 1 (sweep1) / y_r fp16 (sweep2)
#define SM_BIAS 208896                   // 128 floats
#define SM_T    209408
#define SM_IS64 209412
#define SMEM_BYTES 209424

// ---------------- device scratch ----------------
__device__ int   g_counts[NN];
__device__ int   g_offsets[NN];
__device__ int   g_cursor[NN];
__device__ int   g_srcs[NE];
__device__ __align__(16) __half g_xh[(size_t)(NN + TROWS) * DD]; // fp16(x), padded
__device__ __align__(16) __half g_ylh[(size_t)NN * DD];          // x @ Wl.T fp16
__device__ unsigned g_total   = 0;
__device__ unsigned g_tile    = 0;               // sweep1 pool
__device__ unsigned g_tile2   = 0;               // sweep2 pool
__device__ unsigned g_bar_cnt = 0;
__device__ volatile unsigned g_bar_phase = 0;
__device__ unsigned g_bar_dep = 0;
__device__ unsigned g_sub_cnt = 0;               // CSR-group barrier
__device__ volatile unsigned g_sub_phase = 0;
__device__ unsigned g_cvt_cnt = 0;               // GEMM-group (convert) barrier
__device__ volatile unsigned g_cvt_phase = 0;

// ---------------- helpers ----------------
__device__ __forceinline__ uint32_t s2u(const void* p) {
    uint32_t a;
    asm("{ .reg .u64 t; cvta.to.shared.u64 t, %1; cvt.u32.u64 %0, t; }"
        : "=r"(a) : "l"(p));
    return a;
}
__device__ __forceinline__ void ldsm4(uint32_t* r, uint32_t addr) {
    asm volatile("ldmatrix.sync.aligned.m8n8.x4.shared.b16 {%0,%1,%2,%3}, [%4];"
        : "=r"(r[0]), "=r"(r[1]), "=r"(r[2]), "=r"(r[3]) : "r"(addr));
}
__device__ __forceinline__ void mma_f16(float* c, const uint32_t* a,
                                        const uint32_t* b) {
    asm volatile("mma.sync.aligned.m16n8k16.row.col.f32.f16.f16.f32 "
        "{%0,%1,%2,%3}, {%4,%5,%6,%7}, {%8,%9}, {%0,%1,%2,%3};"
        : "+f"(c[0]), "+f"(c[1]), "+f"(c[2]), "+f"(c[3])
        : "r"(a[0]), "r"(a[1]), "r"(a[2]), "r"(a[3]), "r"(b[0]), "r"(b[1]));
}
#define CP_ASYNC16(dst, src) \
    asm volatile("cp.async.cg.shared.global [%0], [%1], 16;" \
                 :: "r"(dst), "l"(src))
#define CP_COMMIT() asm volatile("cp.async.commit_group;" ::: "memory")
#define CP_WAIT0()  asm volatile("cp.async.wait_group 0;"  ::: "memory")

__device__ __forceinline__ int ld_idx(const void* ei, long long pos, int is64) {
    return is64 ? (int)((const long long*)ei)[pos] : ((const int*)ei)[pos];
}
// split 2 consecutive f32 into packed fp16 hi pair + fp16 residual pair
__device__ __forceinline__ void split2h(float f0, float f1, uint32_t& h, uint32_t& l) {
    __half h0 = __float2half_rn(f0);
    __half h1 = __float2half_rn(f1);
    float r0 = f0 - __half2float(h0);
    float r1 = f1 - __half2float(h1);
    __half l0 = __float2half_rn(r0);
    __half l1 = __float2half_rn(r1);
    h = ((uint32_t)__half_as_ushort(h1) << 16) | __half_as_ushort(h0);
    l = ((uint32_t)__half_as_ushort(l1) << 16) | __half_as_ushort(l0);
}

__device__ __forceinline__ void grid_barrier(unsigned use, unsigned ncta) {
    __syncthreads();
    if (threadIdx.x == 0) {
        __threadfence();
        unsigned n = atomicAdd(&g_bar_cnt, 1u);
        if (n == use * ncta - 1u) g_bar_phase = use;
        else while (g_bar_phase < use) __nanosleep(64);
        __threadfence();
    }
    __syncthreads();
}
__device__ __forceinline__ void group_barrier(unsigned* cnt,
                                              volatile unsigned* ph,
                                              unsigned use, unsigned n) {
    __syncthreads();
    if (threadIdx.x == 0) {
        __threadfence();
        unsigned v = atomicAdd(cnt, 1u);
        if (v == use * n - 1u) *ph = use;
        else while (*ph < use) __nanosleep(64);
        __threadfence();
    }
    __syncthreads();
}

// stage one 128-row A tile (fp16, pre-converted) into smem via cp.async
__device__ __forceinline__ void stage_a(uint32_t sb, int row0, int which, int tid) {
    uint32_t ab = sb + (which ? SM_A1 : SM_A0);
    #pragma unroll
    for (int q = 0; q < 4; q++) {
        int c = tid + q * NTHR;          // 0..2047
        int m = c >> 4, ch = c & 15;
        uint32_t dst = ab + m * RSTR + ch * 16;
        const char* src = (const char*)(g_xh + (size_t)(row0 + m) * DD) + ch * 16;
        CP_ASYNC16(dst, src);
    }
}

// ---------------- the persistent mega-kernel ----------------
__global__ void __launch_bounds__(NTHR, 1)
k_mega(const float* __restrict__ x, const void* __restrict__ ei,
       const float* __restrict__ Wl, const float* __restrict__ bl,
       const float* __restrict__ Wr, float* __restrict__ out,
       int ncta, int csrn, int do_tail) {
    extern __shared__ char sm[];
    const uint32_t sb = s2u(sm);
    float* bias = (float*)(sm + SM_BIAS);
    volatile int* sm_t = (volatile int*)(sm + SM_T);

    const int tid  = threadIdx.x;
    const int cta  = blockIdx.x;
    const int wid  = tid >> 5;
    const int lane = tid & 31;
    const int gemn = ncta - csrn;

    // ---- per-CTA init: dtype detect (smem), B staging, bias ----
    if (wid == 0) {
        const int* p = (const int*)ei;
        int v = p[lane * 2 + 1] | p[64 + lane * 2 + 1] |
                p[128 + lane * 2 + 1] | p[192 + lane * 2 + 1];
        unsigned any = __ballot_sync(0xffffffffu, v != 0);
        if (lane == 0) *(volatile int*)(sm + SM_IS64) = (any == 0u);
    }
    // stage B = [Wl;Wr] split hi/lo fp16, [n][k] k-contig, stride 272B
    {
        int n = tid & 255, kh = tid >> 8;      // kh: 0/1 -> k 0..63 / 64..127
        const float* wrow = ((n < 128) ? (Wl + (size_t)n * DD)
                                       : (Wr + (size_t)(n - 128) * DD)) + kh * 64;
        char* bh = sm + SM_BH + n * RSTR + kh * 128;
        char* blo = sm + SM_BL + n * RSTR + kh * 128;
        #pragma unroll
        for (int u = 0; u < 8; u++) {
            float4 v0 = *(const float4*)(wrow + u * 8);
            float4 v1 = *(const float4*)(wrow + u * 8 + 4);
            uint4 hh, ll;
            split2h(v0.x, v0.y, hh.x, ll.x);
            split2h(v0.z, v0.w, hh.y, ll.y);
            split2h(v1.x, v1.y, hh.z, ll.z);
            split2h(v1.z, v1.w, hh.w, ll.w);
            *(uint4*)(bh + u * 16) = hh;
            *(uint4*)(blo + u * 16) = ll;
        }
    }
    if (tid < 128) bias[tid] = bl[tid];
    __syncthreads();
    const int is64 = *(volatile int*)(sm + SM_IS64);

    // ---- CSR group (starts immediately) vs GEMM group (convert+tail) ----
    if (cta < csrn) {
        const int step = csrn * NTHR;
        const int tg = cta * NTHR + tid;
        for (int i = tg; i < NN; i += step) g_counts[i] = 0;
        group_barrier(&g_sub_cnt, &g_sub_phase, 1, (unsigned)csrn);
        for (int e = tg; e < NE; e += step)
            atomicAdd(&g_counts[ld_idx(ei, (long long)NE + e, is64)], 1);
        group_barrier(&g_sub_cnt, &g_sub_phase, 2, (unsigned)csrn);
        for (int wb = cta * NTHR + wid * 32; wb < NN; wb += step) {
            int i = wb + lane;
            int c = (i < NN) ? g_counts[i] : 0;
            int s = c;
            #pragma unroll
            for (int off = 1; off < 32; off <<= 1) {
                int v = __shfl_up_sync(0xffffffffu, s, off);
                if (lane >= off) s += v;
            }
            int tot = __shfl_sync(0xffffffffu, s, 31);
            unsigned base = 0;
            if (lane == 31) base = atomicAdd(&g_total, (unsigned)tot);
            base = __shfl_sync(0xffffffffu, base, 31);
            int excl = (int)base + s - c;
            if (i < NN) { g_offsets[i] = excl; g_cursor[i] = excl; }
        }
        group_barrier(&g_sub_cnt, &g_sub_phase, 3, (unsigned)csrn);
        for (int e = tg; e < NE; e += step) {
            int src = ld_idx(ei, e, is64);
            int dst = ld_idx(ei, (long long)NE + e, is64);
            int p = atomicAdd(&g_cursor[dst], 1);
            g_srcs[p] = src;
        }
        // wait for x->fp16 conversion before joining sweep-1 tile pool
        if (tid == 0) {
            while (g_cvt_phase < 1u) __nanosleep(64);
            __threadfence();
        }
        __syncthreads();
    } else {
        // convert x to fp16 once, striped over GEMM-group CTAs
        const float4* xv = (const float4*)x;
        uint2* xh = (uint2*)g_xh;
        for (int i = (cta - csrn) * NTHR + tid; i < NND / 4; i += gemn * NTHR) {
            float4 v = xv[i];
            __half2 h0 = __floats2half2_rn(v.x, v.y);
            __half2 h1 = __floats2half2_rn(v.z, v.w);
            uint2 u;
            u.x = *(uint32_t*)&h0; u.y = *(uint32_t*)&h1;
            xh[i] = u;
        }
        group_barrier(&g_cvt_cnt, &g_cvt_phase, 1, (unsigned)gemn);
        if (do_tail) {
            for (int t = (cta - csrn) * NTHR + tid; t < 2 * NE; t += gemn * NTHR)
                out[NND + t] = (float)ld_idx(ei, t, is64);
        }
    }

    // ---- SWEEP 1: y_l[128,128] = xh_tile @ Wl^T (1 term), cp.async dbuf ----
    // 16 warps: m32 x n32 each (4x4 grid).
    {
        const int mw = (wid & 3) * 32;
        const int nwB = (wid >> 2) * 32;
        const int g = lane >> 3, r = lane & 7;
        const uint32_t aoff = (uint32_t)((mw + r + (g & 1) * 8) * RSTR + (g >> 1) * 16);
        const uint32_t bhb = sb + SM_BH +
            (uint32_t)((nwB + r + (g >> 1) * 8) * RSTR + (g & 1) * 16);
        const int tr = lane >> 2;
        const int tc = (lane & 3) * 2;

        __syncthreads();
        if (tid == 0) *sm_t = (int)atomicAdd(&g_tile, 1u);
        __syncthreads();
        int t = *sm_t;
        if (t < NT) { stage_a(sb, t * TROWS, 0, tid); CP_COMMIT(); }
        int cur = 0;

        while (t < NT) {
            CP_WAIT0();
            __syncthreads();                  // A visible + prev sm_t consumed
            if (tid == 0) *sm_t = (int)atomicAdd(&g_tile, 1u);
            __syncthreads();                  // sm_t published
            int tn = *sm_t;
            if (tn < NT) { stage_a(sb, tn * TROWS, 1 ^ cur, tid); CP_COMMIT(); }

            int row0 = t * TROWS;
            uint32_t abase = sb + (cur ? SM_A1 : SM_A0) + aoff;

            float acc[2][4][4];
            #pragma unroll
            for (int mi = 0; mi < 2; mi++)
                #pragma unroll
                for (int ni = 0; ni < 4; ni++)
                    #pragma unroll
                    for (int q = 0; q < 4; q++) acc[mi][ni][q] = 0.f;

            #pragma unroll
            for (int k = 0; k < 8; k++) {
                uint32_t a[2][4], b[2][4];
                ldsm4(a[0], abase + k * 32);
                ldsm4(a[1], abase + 16 * RSTR + k * 32);
                ldsm4(b[0], bhb + k * 32);
                ldsm4(b[1], bhb + 16 * RSTR + k * 32);
                #pragma unroll
                for (int mi = 0; mi < 2; mi++)
                    #pragma unroll
                    for (int ni = 0; ni < 4; ni++)
                        mma_f16(acc[mi][ni], a[mi], &b[ni >> 1][(ni & 1) * 2]);
            }

            #pragma unroll
            for (int mi = 0; mi < 2; mi++) {
                #pragma unroll
                for (int rr = 0; rr < 2; rr++) {
                    int row = row0 + mw + mi * 16 + tr + rr * 8;
                    if (row < NN) {
                        __half* dst = g_ylh + (size_t)row * DD + nwB + tc;
                        #pragma unroll
                        for (int ni = 0; ni < 4; ni++) {
                            __half2 hv = __floats2half2_rn(
                                acc[mi][ni][rr * 2], acc[mi][ni][rr * 2 + 1]);
                            *(__half2*)(dst + ni * 8) = hv;
                        }
                    }
                }
            }
            t = tn; cur ^= 1;
        }
    }

    grid_barrier(1, ncta);   // all y_l written + CSR complete

    // ---- SWEEP 2: per tile: y_r (2 terms) -> smem fp16, then aggregate ----
    {
        const int mw = (wid & 3) * 32;
        const int nw = (wid >> 2) * 32;      // local out-col base
        const int g = lane >> 3, r = lane & 7;
        const uint32_t aoff = (uint32_t)((mw + r + (g & 1) * 8) * RSTR + (g >> 1) * 16);
        const uint32_t boff = (uint32_t)((128 + nw + r + (g >> 1) * 8) * RSTR + (g & 1) * 16);
        const uint32_t bhb = sb + SM_BH + boff;
        const uint32_t blb = sb + SM_BL + boff;
        const int tr = lane >> 2;
        const int tc = (lane & 3) * 2;
        const int hw = lane >> 4, hl = lane & 15;
        const unsigned hmask = 0xFFFFu << (hw << 4);
        const uint4* yv = (const uint4*)g_ylh;   // y_l row = 16 uint4

        __syncthreads();
        if (tid == 0) *sm_t = (int)atomicAdd(&g_tile2, 1u);
        __syncthreads();
        int t = *sm_t;
        if (t < NT) { stage_a(sb, t * TROWS, 0, tid); CP_COMMIT(); }

        while (t < NT) {
            CP_WAIT0();
            __syncthreads();                  // A0 ready
            int row0 = t * TROWS;
            uint32_t abase = sb + SM_A0 + aoff;

            float acc[2][4][4];
            #pragma unroll
            for (int mi = 0; mi < 2; mi++)
                #pragma unroll
                for (int ni = 0; ni < 4; ni++)
                    #pragma unroll
                    for (int q = 0; q < 4; q++) acc[mi][ni][q] = 0.f;

            #pragma unroll
            for (int k = 0; k < 8; k++) {
                uint32_t a[2][4], bh[2][4], bl2[2][4];
                ldsm4(a[0], abase + k * 32);
                ldsm4(a[1], abase + 16 * RSTR + k * 32);
                ldsm4(bh[0], bhb + k * 32);
                ldsm4(bh[1], bhb + 16 * RSTR + k * 32);
                ldsm4(bl2[0], blb + k * 32);
                ldsm4(bl2[1], blb + 16 * RSTR + k * 32);
                #pragma unroll
                for (int mi = 0; mi < 2; mi++)
                    #pragma unroll
                    for (int ni = 0; ni < 4; ni++) {
                        mma_f16(acc[mi][ni], a[mi], &bh[ni >> 1][(ni & 1) * 2]);
                        mma_f16(acc[mi][ni], a[mi], &bl2[ni >> 1][(ni & 1) * 2]);
                    }
            }

            // y_r (+bias) -> smem A1 region as fp16, row stride RSTR
            #pragma unroll
            for (int mi = 0; mi < 2; mi++) {
                #pragma unroll
                for (int rr = 0; rr < 2; rr++) {
                    int lr = mw + mi * 16 + tr + rr * 8;
                    #pragma unroll
                    for (int ni = 0; ni < 4; ni++) {
                        int j0 = nw + tc + ni * 8;
                        __half2 hv = __floats2half2_rn(
                            acc[mi][ni][rr * 2]     + bias[j0],
                            acc[mi][ni][rr * 2 + 1] + bias[j0 + 1]);
                        *(__half2*)(sm + SM_A1 + lr * RSTR + j0 * 2) = hv;
                    }
                }
            }
            __syncthreads();                  // y_r complete; A0 reads done
            if (tid == 0) *sm_t = (int)atomicAdd(&g_tile2, 1u);
            __syncthreads();
            int tn = *sm_t;
            if (tn < NT) { stage_a(sb, tn * TROWS, 0, tid); CP_COMMIT(); }

            // aggregate the 128 nodes of this tile: warp -> 8 nodes (2 conc.)
            #pragma unroll 1
            for (int it = 0; it < 4; it++) {
                int nl = wid * 8 + it * 2 + hw;
                int node = row0 + nl;
                if (node < NN) {
                    int start = g_offsets[node];
                    int cnt   = g_counts[node];
                    uint4 uyr = *(const uint4*)(sm + SM_A1 + nl * RSTR + hl * 16);
                    float2 y0 = __half22float2(*(__half2*)&uyr.x);
                    float2 y1 = __half22float2(*(__half2*)&uyr.y);
                    float2 y2 = __half22float2(*(__half2*)&uyr.z);
                    float2 y3 = __half22float2(*(__half2*)&uyr.w);
                    int m1 = 0, m2 = 0;
                    if (hl < cnt)      m1 = g_srcs[start + hl];
                    if (hl + 16 < cnt) m2 = g_srcs[start + hl + 16];
                    float4 a0 = make_float4(0.f, 0.f, 0.f, 0.f);
                    float4 a1 = make_float4(0.f, 0.f, 0.f, 0.f);

#define GACC(u) { \
    float2 p0 = __half22float2(*(__half2*)&(u).x); \
    float2 p1 = __half22float2(*(__half2*)&(u).y); \
    float2 p2 = __half22float2(*(__half2*)&(u).z); \
    float2 p3 = __half22float2(*(__half2*)&(u).w); \
    a0.x += p0.x; a0.y += p0.y; a0.z += p1.x; a0.w += p1.y; \
    a1.x += p2.x; a1.y += p2.y; a1.z += p3.x; a1.w += p3.y; }

                    int nb = cnt < 16 ? cnt : 16;
                    int j = 0;
                    for (; j + 3 < nb; j += 4) {
                        int s0 = __shfl_sync(hmask, m1, j,     16);
                        int s1 = __shfl_sync(hmask, m1, j + 1, 16);
                        int s2 = __shfl_sync(hmask, m1, j + 2, 16);
                        int s3 = __shfl_sync(hmask, m1, j + 3, 16);
                        uint4 u0 = __ldg(&yv[(size_t)s0 * 16 + hl]);
                        uint4 u1 = __ldg(&yv[(size_t)s1 * 16 + hl]);
                        uint4 u2 = __ldg(&yv[(size_t)s2 * 16 + hl]);
                        uint4 u3 = __ldg(&yv[(size_t)s3 * 16 + hl]);
                        GACC(u0); GACC(u1); GACC(u2); GACC(u3);
                    }
                    for (; j < nb; j++) {
                        int s0 = __shfl_sync(hmask, m1, j, 16);
                        uint4 u0 = __ldg(&yv[(size_t)s0 * 16 + hl]);
                        GACC(u0);
                    }
                    int nb2 = cnt < 32 ? cnt : 32;
                    for (j = 16; j < nb2; j++) {
                        int s0 = __shfl_sync(hmask, m2, j - 16, 16);
                        uint4 u0 = __ldg(&yv[(size_t)s0 * 16 + hl]);
                        GACC(u0);
                    }
                    for (int i = 32; i < cnt; i++) {    // rare deg > 32
                        int s0 = g_srcs[start + i];
                        uint4 u0 = __ldg(&yv[(size_t)s0 * 16 + hl]);
                        GACC(u0);
                    }
#undef GACC
                    float inv = 1.0f / fmaxf((float)cnt, 1.0f);
                    float o0 = a0.x * inv + y0.x;
                    float o1 = a0.y * inv + y0.y;
                    float o2 = a0.z * inv + y1.x;
                    float o3 = a0.w * inv + y1.y;
                    float o4 = a1.x * inv + y2.x;
                    float o5 = a1.y * inv + y2.y;
                    float o6 = a1.z * inv + y3.x;
                    float o7 = a1.w * inv + y3.y;
                    o0 = (o0 > 0.f) ? o0 : (__expf(o0) - 1.f);
                    o1 = (o1 > 0.f) ? o1 : (__expf(o1) - 1.f);
                    o2 = (o2 > 0.f) ? o2 : (__expf(o2) - 1.f);
                    o3 = (o3 > 0.f) ? o3 : (__expf(o3) - 1.f);
                    o4 = (o4 > 0.f) ? o4 : (__expf(o4) - 1.f);
                    o5 = (o5 > 0.f) ? o5 : (__expf(o5) - 1.f);
                    o6 = (o6 > 0.f) ? o6 : (__expf(o6) - 1.f);
                    o7 = (o7 > 0.f) ? o7 : (__expf(o7) - 1.f);
                    float4* orow = (float4*)(out + (size_t)node * DD);
                    orow[hl * 2]     = make_float4(o0, o1, o2, o3);
                    orow[hl * 2 + 1] = make_float4(o4, o5, o6, o7);
                }
            }
            __syncthreads();                  // A1 free for next tile
            t = tn;
        }
    }

    // ---- depart: last CTA out resets all cross-launch state ----
    __syncthreads();
    if (tid == 0) {
        __threadfence();
        unsigned d = atomicAdd(&g_bar_dep, 1u);
        if (d == (unsigned)ncta - 1u) {
            g_bar_cnt = 0; g_bar_phase = 0; g_bar_dep = 0;
            g_sub_cnt = 0; g_sub_phase = 0;
            g_cvt_cnt = 0; g_cvt_phase = 0;
            g_tile = 0;    g_tile2 = 0;  g_total = 0;
        }
    }
}

// ---------------- launch ----------------
extern "C" void kernel_launch(void* const* d_in, const int* in_sizes, int n_in,
                              void* d_out, int out_size) {
    const float* x  = (const float*)d_in[0];
    const void*  ei = d_in[1];
    const float* Wl = (const float*)d_in[2];
    const float* bl = (const float*)d_in[3];
    const float* Wr = (const float*)d_in[4];
    float* out = (float*)d_out;

    int dev = 0;
    cudaGetDevice(&dev);
    int ncta = 0;
    cudaDeviceGetAttribute(&ncta, cudaDevAttrMultiProcessorCount, dev);
    if (ncta <= 0) ncta = 148;
    int csrn = ncta / 3;
    if (csrn < 1) csrn = 1;
    int do_tail = (out_size >= NND + 2 * NE) ? 1 : 0;

    cudaFuncSetAttribute(k_mega, cudaFuncAttributeMaxDynamicSharedMemorySize,
                         SMEM_BYTES);
    k_mega<<<ncta, NTHR, SMEM_BYTES>>>(x, ei, Wl, bl, Wr, out,
                                       ncta, csrn, do_tail);
}

// round 16
// speedup vs baseline: 1.1384x; 1.1384x over previous
#include <cuda_runtime.h>
#include <cuda_fp16.h>
#include <math.h>
#include <stdint.h>

#define NN 50000
#define NE 600000
#define DD 128
#define NND (NN * DD)
#define TROWS 128
#define NT ((NN + TROWS - 1) / TROWS)   // 391 tiles
#define NTHR 512
#define RSTR 272                         // smem row stride in bytes (17*16)

// ---- smem byte offsets ----
#define SM_BH   0                        // B-hi: 256 rows x 272B
#define SM_BL   69632                    // B-lo
#define SM_A0   139264                   // A buf 0: 128 rows x 272B
#define SM_A1   174080                   // A buf 1
#define SM_BIAS 208896                   // 128 floats
#define SM_T    209408
#define SM_IS64 209412
#define SMEM_BYTES 209424

// ---------------- device scratch ----------------
__device__ int   g_counts[NN];
__device__ int   g_offsets[NN];
__device__ int   g_cursor[NN];
__device__ int   g_srcs[NE];
__device__ __align__(16) __half g_xh[(size_t)(NN + TROWS) * DD]; // fp16(x), padded
__device__ __align__(16) __half g_ylh[(size_t)NN * DD];          // x @ Wl.T fp16
__device__ __align__(16) __half g_yrh[(size_t)NN * DD];          // x @ Wr.T + b fp16
__device__ unsigned g_total   = 0;
__device__ unsigned g_tile    = 0;
__device__ unsigned g_bar_cnt = 0;
__device__ volatile unsigned g_bar_phase = 0;
__device__ unsigned g_bar_dep = 0;
__device__ unsigned g_sub_cnt = 0;               // CSR-group barrier
__device__ volatile unsigned g_sub_phase = 0;
__device__ unsigned g_cvt_cnt = 0;               // GEMM-group (convert) barrier
__device__ volatile unsigned g_cvt_phase = 0;

// ---------------- helpers ----------------
__device__ __forceinline__ uint32_t s2u(const void* p) {
    uint32_t a;
    asm("{ .reg .u64 t; cvta.to.shared.u64 t, %1; cvt.u32.u64 %0, t; }"
        : "=r"(a) : "l"(p));
    return a;
}
__device__ __forceinline__ void ldsm4(uint32_t* r, uint32_t addr) {
    asm volatile("ldmatrix.sync.aligned.m8n8.x4.shared.b16 {%0,%1,%2,%3}, [%4];"
        : "=r"(r[0]), "=r"(r[1]), "=r"(r[2]), "=r"(r[3]) : "r"(addr));
}
__device__ __forceinline__ void mma_f16(float* c, const uint32_t* a,
                                        const uint32_t* b) {
    asm volatile("mma.sync.aligned.m16n8k16.row.col.f32.f16.f16.f32 "
        "{%0,%1,%2,%3}, {%4,%5,%6,%7}, {%8,%9}, {%0,%1,%2,%3};"
        : "+f"(c[0]), "+f"(c[1]), "+f"(c[2]), "+f"(c[3])
        : "r"(a[0]), "r"(a[1]), "r"(a[2]), "r"(a[3]), "r"(b[0]), "r"(b[1]));
}
#define CP_ASYNC16(dst, src) \
    asm volatile("cp.async.cg.shared.global [%0], [%1], 16;" \
                 :: "r"(dst), "l"(src))
#define CP_COMMIT() asm volatile("cp.async.commit_group;" ::: "memory")
#define CP_WAIT0()  asm volatile("cp.async.wait_group 0;"  ::: "memory")

__device__ __forceinline__ int ld_idx(const void* ei, long long pos, int is64) {
    return is64 ? (int)((const long long*)ei)[pos] : ((const int*)ei)[pos];
}
// split 2 consecutive f32 into packed fp16 hi pair + fp16 residual pair
__device__ __forceinline__ void split2h(float f0, float f1, uint32_t& h, uint32_t& l) {
    __half h0 = __float2half_rn(f0);
    __half h1 = __float2half_rn(f1);
    float r0 = f0 - __half2float(h0);
    float r1 = f1 - __half2float(h1);
    __half l0 = __float2half_rn(r0);
    __half l1 = __float2half_rn(r1);
    h = ((uint32_t)__half_as_ushort(h1) << 16) | __half_as_ushort(h0);
    l = ((uint32_t)__half_as_ushort(l1) << 16) | __half_as_ushort(l0);
}

__device__ __forceinline__ void grid_barrier(unsigned use, unsigned ncta) {
    __syncthreads();
    if (threadIdx.x == 0) {
        __threadfence();
        unsigned n = atomicAdd(&g_bar_cnt, 1u);
        if (n == use * ncta - 1u) g_bar_phase = use;
        else while (g_bar_phase < use) __nanosleep(64);
        __threadfence();
    }
    __syncthreads();
}
__device__ __forceinline__ void group_barrier(unsigned* cnt,
                                              volatile unsigned* ph,
                                              unsigned use, unsigned n) {
    __syncthreads();
    if (threadIdx.x == 0) {
        __threadfence();
        unsigned v = atomicAdd(cnt, 1u);
        if (v == use * n - 1u) *ph = use;
        else while (*ph < use) __nanosleep(64);
        __threadfence();
    }
    __syncthreads();
}

// stage one 128-row A tile (fp16, pre-converted) into smem via cp.async
__device__ __forceinline__ void stage_a(uint32_t sb, int row0, int which, int tid) {
    uint32_t ab = sb + (which ? SM_A1 : SM_A0);
    #pragma unroll
    for (int q = 0; q < 4; q++) {
        int c = tid + q * NTHR;          // 0..2047
        int m = c >> 4, ch = c & 15;
        uint32_t dst = ab + m * RSTR + ch * 16;
        const char* src = (const char*)(g_xh + (size_t)(row0 + m) * DD) + ch * 16;
        CP_ASYNC16(dst, src);
    }
}

// ---------------- the persistent mega-kernel ----------------
__global__ void __launch_bounds__(NTHR, 1)
k_mega(const float* __restrict__ x, const void* __restrict__ ei,
       const float* __restrict__ Wl, const float* __restrict__ bl,
       const float* __restrict__ Wr, float* __restrict__ out,
       int ncta, int csrn, int do_tail) {
    extern __shared__ char sm[];
    const uint32_t sb = s2u(sm);
    float* bias = (float*)(sm + SM_BIAS);
    volatile int* sm_t = (volatile int*)(sm + SM_T);

    const int tid  = threadIdx.x;
    const int cta  = blockIdx.x;
    const int wid  = tid >> 5;
    const int lane = tid & 31;
    const int gemn = ncta - csrn;

    // ---- per-CTA init: dtype detect (smem), B staging, bias ----
    if (wid == 0) {
        const int* p = (const int*)ei;
        int v = p[lane * 2 + 1] | p[64 + lane * 2 + 1] |
                p[128 + lane * 2 + 1] | p[192 + lane * 2 + 1];
        unsigned any = __ballot_sync(0xffffffffu, v != 0);
        if (lane == 0) *(volatile int*)(sm + SM_IS64) = (any == 0u);
    }
    // stage B = [Wl;Wr] split hi/lo fp16, [n][k] k-contig, stride 272B
    {
        int n = tid & 255, kh = tid >> 8;      // kh: 0/1 -> k 0..63 / 64..127
        const float* wrow = ((n < 128) ? (Wl + (size_t)n * DD)
                                       : (Wr + (size_t)(n - 128) * DD)) + kh * 64;
        char* bh = sm + SM_BH + n * RSTR + kh * 128;
        char* blo = sm + SM_BL + n * RSTR + kh * 128;
        #pragma unroll
        for (int u = 0; u < 8; u++) {
            float4 v0 = *(const float4*)(wrow + u * 8);
            float4 v1 = *(const float4*)(wrow + u * 8 + 4);
            uint4 hh, ll;
            split2h(v0.x, v0.y, hh.x, ll.x);
            split2h(v0.z, v0.w, hh.y, ll.y);
            split2h(v1.x, v1.y, hh.z, ll.z);
            split2h(v1.z, v1.w, hh.w, ll.w);
            *(uint4*)(bh + u * 16) = hh;
            *(uint4*)(blo + u * 16) = ll;
        }
    }
    if (tid < 128) bias[tid] = bl[tid];
    __syncthreads();
    const int is64 = *(volatile int*)(sm + SM_IS64);

    // ---- CSR group (starts immediately) vs GEMM group (convert+tail) ----
    if (cta < csrn) {
        const int step = csrn * NTHR;
        const int tg = cta * NTHR + tid;
        for (int i = tg; i < NN; i += step) g_counts[i] = 0;
        group_barrier(&g_sub_cnt, &g_sub_phase, 1, (unsigned)csrn);
        for (int e = tg; e < NE; e += step)
            atomicAdd(&g_counts[ld_idx(ei, (long long)NE + e, is64)], 1);
        group_barrier(&g_sub_cnt, &g_sub_phase, 2, (unsigned)csrn);
        for (int wb = cta * NTHR + wid * 32; wb < NN; wb += step) {
            int i = wb + lane;
            int c = (i < NN) ? g_counts[i] : 0;
            int s = c;
            #pragma unroll
            for (int off = 1; off < 32; off <<= 1) {
                int v = __shfl_up_sync(0xffffffffu, s, off);
                if (lane >= off) s += v;
            }
            int tot = __shfl_sync(0xffffffffu, s, 31);
            unsigned base = 0;
            if (lane == 31) base = atomicAdd(&g_total, (unsigned)tot);
            base = __shfl_sync(0xffffffffu, base, 31);
            int excl = (int)base + s - c;
            if (i < NN) { g_offsets[i] = excl; g_cursor[i] = excl; }
        }
        group_barrier(&g_sub_cnt, &g_sub_phase, 3, (unsigned)csrn);
        for (int e = tg; e < NE; e += step) {
            int src = ld_idx(ei, e, is64);
            int dst = ld_idx(ei, (long long)NE + e, is64);
            int p = atomicAdd(&g_cursor[dst], 1);
            g_srcs[p] = src;
        }
        // wait for x->fp16 conversion before joining GEMM tile pool
        if (tid == 0) {
            while (g_cvt_phase < 1u) __nanosleep(64);
            __threadfence();
        }
        __syncthreads();
    } else {
        // convert x to fp16 once, striped over GEMM-group CTAs
        const float4* xv = (const float4*)x;
        uint2* xh = (uint2*)g_xh;
        for (int i = (cta - csrn) * NTHR + tid; i < NND / 4; i += gemn * NTHR) {
            float4 v = xv[i];
            __half2 h0 = __floats2half2_rn(v.x, v.y);
            __half2 h1 = __floats2half2_rn(v.z, v.w);
            uint2 u;
            u.x = *(uint32_t*)&h0; u.y = *(uint32_t*)&h1;
            xh[i] = u;
        }
        group_barrier(&g_cvt_cnt, &g_cvt_phase, 1, (unsigned)gemn);
        if (do_tail) {
            for (int t = (cta - csrn) * NTHR + tid; t < 2 * NE; t += gemn * NTHR)
                out[NND + t] = (float)ld_idx(ei, t, is64);
        }
    }

    // ---- GEMM: D[128,256] = xh_tile @ [Wl;Wr]^T, 2 B-terms, cp.async dbuf ----
    {
        const int mw = (wid & 3) * 32;
        const int nw = (wid >> 2) * 64;
        const int g = lane >> 3, r = lane & 7;
        const uint32_t aoff = (uint32_t)((mw + r + (g & 1) * 8) * RSTR + (g >> 1) * 16);
        const uint32_t boff = (uint32_t)((nw + r + (g >> 1) * 8) * RSTR + (g & 1) * 16);
        const uint32_t bhb = sb + SM_BH + boff;
        const uint32_t blb = sb + SM_BL + boff;
        const int tr = lane >> 2;
        const int tc = (lane & 3) * 2;

        __syncthreads();
        if (tid == 0) *sm_t = (int)atomicAdd(&g_tile, 1u);
        __syncthreads();
        int t = *sm_t;
        if (t < NT) { stage_a(sb, t * TROWS, 0, tid); CP_COMMIT(); }
        int cur = 0;

        while (t < NT) {
            CP_WAIT0();
            // barrier 1: staged A visible + all warps past previous sm_t use
            __syncthreads();
            if (tid == 0) *sm_t = (int)atomicAdd(&g_tile, 1u);
            __syncthreads();                  // barrier 2: sm_t published
            int tn = *sm_t;
            if (tn < NT) { stage_a(sb, tn * TROWS, 1 ^ cur, tid); CP_COMMIT(); }

            int row0 = t * TROWS;
            uint32_t abase = sb + (cur ? SM_A1 : SM_A0) + aoff;

            float acc[2][8][4];
            #pragma unroll
            for (int mi = 0; mi < 2; mi++)
                #pragma unroll
                for (int ni = 0; ni < 8; ni++)
                    #pragma unroll
                    for (int q = 0; q < 4; q++) acc[mi][ni][q] = 0.f;

            #pragma unroll
            for (int k = 0; k < 8; k++) {
                uint32_t a[2][4], bh[4][4], bl2[4][4];
                ldsm4(a[0], abase + k * 32);
                ldsm4(a[1], abase + 16 * RSTR + k * 32);
                #pragma unroll
                for (int bg = 0; bg < 4; bg++) {
                    ldsm4(bh[bg],  bhb + bg * 16 * RSTR + k * 32);
                    ldsm4(bl2[bg], blb + bg * 16 * RSTR + k * 32);
                }
                #pragma unroll
                for (int mi = 0; mi < 2; mi++)
                    #pragma unroll
                    for (int ni = 0; ni < 8; ni++) {
                        mma_f16(acc[mi][ni], a[mi], &bh[ni >> 1][(ni & 1) * 2]);
                        mma_f16(acc[mi][ni], a[mi], &bl2[ni >> 1][(ni & 1) * 2]);
                    }
            }

            // epilogue: nw<128 -> g_ylh ; nw>=128 -> g_yrh (+bias), both fp16
            #pragma unroll
            for (int mi = 0; mi < 2; mi++) {
                #pragma unroll
                for (int rr = 0; rr < 2; rr++) {
                    int row = row0 + mw + mi * 16 + tr + rr * 8;
                    if (row < NN) {
                        if (nw < 128) {
                            __half* dst = g_ylh + (size_t)row * DD + nw + tc;
                            #pragma unroll
                            for (int ni = 0; ni < 8; ni++) {
                                __half2 hv = __floats2half2_rn(
                                    acc[mi][ni][rr * 2], acc[mi][ni][rr * 2 + 1]);
                                *(__half2*)(dst + ni * 8) = hv;
                            }
                        } else {
                            int j0 = nw - 128 + tc;
                            __half* dst = g_yrh + (size_t)row * DD + j0;
                            #pragma unroll
                            for (int ni = 0; ni < 8; ni++) {
                                __half2 hv = __floats2half2_rn(
                                    acc[mi][ni][rr * 2]     + bias[j0 + ni * 8],
                                    acc[mi][ni][rr * 2 + 1] + bias[j0 + ni * 8 + 1]);
                                *(__half2*)(dst + ni * 8) = hv;
                            }
                        }
                    }
                }
            }
            t = tn; cur ^= 1;
        }
    }

    grid_barrier(1, ncta);

    // ---- aggregate: out = ELU(mean(y_l[src]) + y_r), HALF-warp per node ----
    // Per-segment shuffle masks (half-warps have independent trip counts).
    {
        const int hw = lane >> 4, hl = lane & 15;
        const unsigned hmask = 0xFFFFu << (hw << 4);
        const uint4* yv  = (const uint4*)g_ylh;  // row = 16 uint4
        const uint4* yrv = (const uint4*)g_yrh;
        for (int node = cta * 32 + wid * 2 + hw; node < NN; node += ncta * 32) {
            int start = g_offsets[node];
            int cnt   = g_counts[node];
            uint4 uyr = __ldg(&yrv[(size_t)node * 16 + hl]);
            float2 y0 = __half22float2(*(__half2*)&uyr.x);
            float2 y1 = __half22float2(*(__half2*)&uyr.y);
            float2 y2 = __half22float2(*(__half2*)&uyr.z);
            float2 y3 = __half22float2(*(__half2*)&uyr.w);
            int m1 = 0, m2 = 0;
            if (hl < cnt)      m1 = g_srcs[start + hl];
            if (hl + 16 < cnt) m2 = g_srcs[start + hl + 16];
            float4 a0 = make_float4(0.f, 0.f, 0.f, 0.f);
            float4 a1 = make_float4(0.f, 0.f, 0.f, 0.f);

#define GACC(u) { \
    float2 p0 = __half22float2(*(__half2*)&(u).x); \
    float2 p1 = __half22float2(*(__half2*)&(u).y); \
    float2 p2 = __half22float2(*(__half2*)&(u).z); \
    float2 p3 = __half22float2(*(__half2*)&(u).w); \
    a0.x += p0.x; a0.y += p0.y; a0.z += p1.x; a0.w += p1.y; \
    a1.x += p2.x; a1.y += p2.y; a1.z += p3.x; a1.w += p3.y; }

            int nb = cnt < 16 ? cnt : 16;
            int j = 0;
            for (; j + 3 < nb; j += 4) {
                int s0 = __shfl_sync(hmask, m1, j,     16);
                int s1 = __shfl_sync(hmask, m1, j + 1, 16);
                int s2 = __shfl_sync(hmask, m1, j + 2, 16);
                int s3 = __shfl_sync(hmask, m1, j + 3, 16);
                uint4 u0 = __ldg(&yv[(size_t)s0 * 16 + hl]);
                uint4 u1 = __ldg(&yv[(size_t)s1 * 16 + hl]);
                uint4 u2 = __ldg(&yv[(size_t)s2 * 16 + hl]);
                uint4 u3 = __ldg(&yv[(size_t)s3 * 16 + hl]);
                GACC(u0); GACC(u1); GACC(u2); GACC(u3);
            }
            for (; j < nb; j++) {
                int s0 = __shfl_sync(hmask, m1, j, 16);
                uint4 u0 = __ldg(&yv[(size_t)s0 * 16 + hl]);
                GACC(u0);
            }
            int nb2 = cnt < 32 ? cnt : 32;
            for (j = 16; j < nb2; j++) {
                int s0 = __shfl_sync(hmask, m2, j - 16, 16);
                uint4 u0 = __ldg(&yv[(size_t)s0 * 16 + hl]);
                GACC(u0);
            }
            for (int i = 32; i < cnt; i++) {        // rare overflow (deg > 32)
                int s0 = g_srcs[start + i];
                uint4 u0 = __ldg(&yv[(size_t)s0 * 16 + hl]);
                GACC(u0);
            }
#undef GACC
            float inv = 1.0f / fmaxf((float)cnt, 1.0f);
            float o0 = a0.x * inv + y0.x;
            float o1 = a0.y * inv + y0.y;
            float o2 = a0.z * inv + y1.x;
            float o3 = a0.w * inv + y1.y;
            float o4 = a1.x * inv + y2.x;
            float o5 = a1.y * inv + y2.y;
            float o6 = a1.z * inv + y3.x;
            float o7 = a1.w * inv + y3.y;
            o0 = (o0 > 0.f) ? o0 : (__expf(o0) - 1.f);
            o1 = (o1 > 0.f) ? o1 : (__expf(o1) - 1.f);
            o2 = (o2 > 0.f) ? o2 : (__expf(o2) - 1.f);
            o3 = (o3 > 0.f) ? o3 : (__expf(o3) - 1.f);
            o4 = (o4 > 0.f) ? o4 : (__expf(o4) - 1.f);
            o5 = (o5 > 0.f) ? o5 : (__expf(o5) - 1.f);
            o6 = (o6 > 0.f) ? o6 : (__expf(o6) - 1.f);
            o7 = (o7 > 0.f) ? o7 : (__expf(o7) - 1.f);
            float4* orow = (float4*)(out + (size_t)node * DD);
            orow[hl * 2]     = make_float4(o0, o1, o2, o3);
            orow[hl * 2 + 1] = make_float4(o4, o5, o6, o7);
        }
    }

    // ---- depart: last CTA out resets all cross-launch state ----
    __syncthreads();
    if (tid == 0) {
        __threadfence();
        unsigned d = atomicAdd(&g_bar_dep, 1u);
        if (d == (unsigned)ncta - 1u) {
            g_bar_cnt = 0; g_bar_phase = 0; g_bar_dep = 0;
            g_sub_cnt = 0; g_sub_phase = 0;
            g_cvt_cnt = 0; g_cvt_phase = 0;
            g_tile = 0;    g_total = 0;
        }
    }
}

// ---------------- launch ----------------
extern "C" void kernel_launch(void* const* d_in, const int* in_sizes, int n_in,
                              void* d_out, int out_size) {
    const float* x  = (const float*)d_in[0];
    const void*  ei = d_in[1];
    const float* Wl = (const float*)d_in[2];
    const float* bl = (const float*)d_in[3];
    const float* Wr = (const float*)d_in[4];
    float* out = (float*)d_out;

    int dev = 0;
    cudaGetDevice(&dev);
    int ncta = 0;
    cudaDeviceGetAttribute(&ncta, cudaDevAttrMultiProcessorCount, dev);
    if (ncta <= 0) ncta = 148;
    int csrn = (ncta * 3) / 8;           // 57 on 152 SMs (CSR leg near-critical)
    if (csrn < 1) csrn = 1;
    int do_tail = (out_size >= NND + 2 * NE) ? 1 : 0;

    cudaFuncSetAttribute(k_mega, cudaFuncAttributeMaxDynamicSharedMemorySize,
                         SMEM_BYTES);
    k_mega<<<ncta, NTHR, SMEM_BYTES>>>(x, ei, Wl, bl, Wr, out,
                                       ncta, csrn, do_tail);
}